// round 5
// baseline (speedup 1.0000x reference)
#include <cuda_runtime.h>

#define FDIM 128
#define MAXN 50000
#define MAXE 800000

// ---------------- scratch (static device globals; no allocation) ------------
__device__ int   g_flag;                 // 1 => edge_index is int32, 0 => int64
__device__ int   g_row[MAXE];
__device__ int   g_col[MAXE];
__device__ int   g_srt[MAXE];            // edge sources sorted by destination (CSR)
__device__ int   g_cnt[MAXN];
__device__ int   g_cstart[MAXN + 1];
__device__ int   g_cursor[MAXN];
__device__ int   g_bsum[64];
__device__ int   g_boff[64];
__device__ float g_dinv[MAXN];
__device__ float g_buf1[(size_t)MAXN * FDIM];   // GEMM outputs
__device__ float g_buf2[(size_t)MAXN * FDIM];   // aggregation outputs

// ---------------- setup kernels --------------------------------------------
__global__ void k_init(int Nn) {
    int i = blockIdx.x * blockDim.x + threadIdx.x;
    if (i < Nn) g_cnt[i] = 0;
    if (i == 0) g_flag = 0;
}

// Inspect 32-bit words of the edge buffer. If dtype is int64 (values in
// [0, 50000)), every odd 32-bit word is zero (little-endian). If int32, the
// odd words are random node ids (nonzero with overwhelming probability over
// 32K samples).
__global__ void k_detect(const unsigned int* __restrict__ buf, int nwords) {
    int i = blockIdx.x * blockDim.x + threadIdx.x;   // 0 .. 32767
    int idx = 2 * i + 1;
    if (idx < nwords && buf[idx] != 0u) g_flag = 1;  // benign race, all write 1
}

__global__ void k_convert(const void* __restrict__ buf, int E) {
    int e = blockIdx.x * blockDim.x + threadIdx.x;
    if (e >= E) return;
    if (g_flag == 0) {
        const long long* p = (const long long*)buf;
        g_row[e] = (int)p[e];
        g_col[e] = (int)p[(size_t)E + e];
    } else {
        const int* p = (const int*)buf;
        g_row[e] = p[e];
        g_col[e] = p[E + e];
    }
}

__global__ void k_count(int E) {
    int e = blockIdx.x * blockDim.x + threadIdx.x;
    if (e < E) atomicAdd(&g_cnt[g_col[e]], 1);
}

__global__ void k_dinv(int Nn) {
    int i = blockIdx.x * blockDim.x + threadIdx.x;
    if (i < Nn) g_dinv[i] = rsqrtf((float)(g_cnt[i] + 1));  // +1 self loop
}

// ---------------- exclusive scan over g_cnt (N <= 50000) -------------------
__global__ void k_scan1(int Nn) {
    __shared__ int s[1024];
    int tid = threadIdx.x;
    int i = blockIdx.x * 1024 + tid;
    int v = (i < Nn) ? g_cnt[i] : 0;
    s[tid] = v;
    __syncthreads();
    for (int off = 1; off < 1024; off <<= 1) {
        int t = (tid >= off) ? s[tid - off] : 0;
        __syncthreads();
        s[tid] += t;
        __syncthreads();
    }
    if (i < Nn) g_cstart[i] = s[tid] - v;       // block-local exclusive
    if (tid == 1023) g_bsum[blockIdx.x] = s[1023];
}

__global__ void k_scan2(int NB) {
    __shared__ int s[64];
    int tid = threadIdx.x;
    int v = (tid < NB) ? g_bsum[tid] : 0;
    s[tid] = v;
    __syncthreads();
    for (int off = 1; off < 64; off <<= 1) {
        int t = (tid >= off) ? s[tid - off] : 0;
        __syncthreads();
        s[tid] += t;
        __syncthreads();
    }
    g_boff[tid] = s[tid] - v;
}

__global__ void k_scan3(int Nn, int E) {
    int i = blockIdx.x * blockDim.x + threadIdx.x;
    if (i < Nn) {
        int v = g_cstart[i] + g_boff[i >> 10];
        g_cstart[i] = v;
        g_cursor[i] = v;
    }
    if (i == 0) g_cstart[Nn] = E;
}

__global__ void k_scatter(int E) {
    int e = blockIdx.x * blockDim.x + threadIdx.x;
    if (e < E) {
        int c = g_col[e];
        int p = atomicAdd(&g_cursor[c], 1);
        g_srt[p] = g_row[e];
    }
}

// ---------------- GEMM: out[N,128] = A[N,128] @ W[128,128] -----------------
// 64x128 tile per block, 256 threads, each thread computes 8x4 micro-tile.
__device__ __forceinline__ void gemm_128(const float* __restrict__ A,
                                         const float* __restrict__ W,
                                         float* __restrict__ out, int Nn) {
    __shared__ __align__(16) float As[64][16];
    __shared__ __align__(16) float Ws[16][128];
    int t = threadIdx.x;
    int row0 = blockIdx.x * 64;
    int ty = t >> 5;        // 0..7  -> rows [ty*8, ty*8+8)
    int tx = t & 31;        // 0..31 -> cols [tx*4, tx*4+4)

    float acc[8][4];
#pragma unroll
    for (int r = 0; r < 8; r++)
#pragma unroll
        for (int c = 0; c < 4; c++) acc[r][c] = 0.f;

    for (int k0 = 0; k0 < 128; k0 += 16) {
        // A tile: 64 rows x 16 k (one float4 per thread)
        int lr = t >> 2;
        int lk = (t & 3) << 2;
        int grow = row0 + lr;
        float4 av = make_float4(0.f, 0.f, 0.f, 0.f);
        if (grow < Nn) av = *(const float4*)(A + (size_t)grow * FDIM + k0 + lk);
        *(float4*)&As[lr][lk] = av;
        // W tile: 16 k x 128 cols (two float4s per thread)
#pragma unroll
        for (int tt = 0; tt < 2; tt++) {
            int lin = t + tt * 256;
            int wk = lin >> 5;
            int wc = (lin & 31) << 2;
            *(float4*)&Ws[wk][wc] = *(const float4*)(W + (size_t)(k0 + wk) * FDIM + wc);
        }
        __syncthreads();
#pragma unroll
        for (int kk = 0; kk < 16; kk++) {
            float4 b = *(const float4*)&Ws[kk][tx << 2];
#pragma unroll
            for (int r = 0; r < 8; r++) {
                float a = As[ty * 8 + r][kk];
                acc[r][0] += a * b.x;
                acc[r][1] += a * b.y;
                acc[r][2] += a * b.z;
                acc[r][3] += a * b.w;
            }
        }
        __syncthreads();
    }
#pragma unroll
    for (int r = 0; r < 8; r++) {
        int row = row0 + ty * 8 + r;
        if (row < Nn) {
            float4 o = make_float4(acc[r][0], acc[r][1], acc[r][2], acc[r][3]);
            *(float4*)(out + (size_t)row * FDIM + (tx << 2)) = o;
        }
    }
}

__global__ void __launch_bounds__(256)
k_gemm1(const float* __restrict__ x, const float* __restrict__ W, int Nn) {
    gemm_128(x, W, g_buf1, Nn);
}

__global__ void __launch_bounds__(256)
k_gemm2(const float* __restrict__ W, int Nn) {
    gemm_128(g_buf2, W, g_buf1, Nn);
}

// ---------------- aggregation: buf2[j] = sum_{r in N(j)} norm * buf1[r] + b --
// One warp per destination node; lane handles 4 features (float4).
// Neighbor index + dinv prefetched one iteration ahead to hide LDG latency.
__global__ void __launch_bounds__(256)
k_agg(const float* __restrict__ bias, int Nn) {
    int wid = (blockIdx.x * blockDim.x + threadIdx.x) >> 5;
    int lane = threadIdx.x & 31;
    if (wid >= Nn) return;
    int j = wid;
    float dj = g_dinv[j];
    float4 hv = ((const float4*)(g_buf1 + (size_t)j * FDIM))[lane];
    float w0 = dj * dj;                              // self loop
    float ax = w0 * hv.x, ay = w0 * hv.y, az = w0 * hv.z, aw = w0 * hv.w;
    int s = g_cstart[j], e = g_cstart[j + 1];

    if (s < e) {
        int   r_nxt = g_srt[s];
        float d_nxt = g_dinv[r_nxt];
        for (int idx = s; idx < e; ++idx) {
            int   r  = r_nxt;
            float dr = d_nxt;
            if (idx + 1 < e) {
                r_nxt = g_srt[idx + 1];
                d_nxt = g_dinv[r_nxt];
            }
            float wr = dj * dr;
            float4 hr = ((const float4*)(g_buf1 + (size_t)r * FDIM))[lane];
            ax += wr * hr.x;
            ay += wr * hr.y;
            az += wr * hr.z;
            aw += wr * hr.w;
        }
    }
    float4 b4 = ((const float4*)bias)[lane];
    float4 o = make_float4(ax + b4.x, ay + b4.y, az + b4.z, aw + b4.w);
    ((float4*)(g_buf2 + (size_t)j * FDIM))[lane] = o;
}

// ---------------- final FC: out[N,8] = buf2[N,128] @ Wfc[128,8] + bfc -------
__global__ void __launch_bounds__(256)
k_fc(const float* __restrict__ Wfc, const float* __restrict__ bfc,
     float* __restrict__ out, int Nn) {
    __shared__ float Ws[128 * 8];
    __shared__ float bs[8];
    for (int i = threadIdx.x; i < 1024; i += 256) Ws[i] = Wfc[i];
    if (threadIdx.x < 8) bs[threadIdx.x] = bfc[threadIdx.x];
    __syncthreads();
    int gid = blockIdx.x * blockDim.x + threadIdx.x;
    int n = gid >> 3, c = gid & 7;
    if (n >= Nn) return;
    const float* hp = g_buf2 + (size_t)n * FDIM;
    float acc = 0.f;
#pragma unroll
    for (int k = 0; k < 128; k++) acc += hp[k] * Ws[k * 8 + c];
    out[gid] = acc + bs[c];
}

// ---------------- launch ----------------------------------------------------
extern "C" void kernel_launch(void* const* d_in, const int* in_sizes, int n_in,
                              void* d_out, int out_size) {
    const float* x   = (const float*)d_in[0];
    const void*  ei  = d_in[1];
    const float* W1  = (const float*)d_in[2];
    const float* b1  = (const float*)d_in[3];
    const float* W2  = (const float*)d_in[4];
    const float* b2  = (const float*)d_in[5];
    const float* Wfc = (const float*)d_in[6];
    const float* bfc = (const float*)d_in[7];
    float* out = (float*)d_out;

    int Nn = in_sizes[0] / FDIM;
    int E  = in_sizes[1] / 2;
    if (Nn > MAXN) Nn = MAXN;
    if (E > MAXE)  E = MAXE;

    int gE = (E + 255) / 256;
    int gN = (Nn + 255) / 256;
    int NB = (Nn + 1023) / 1024;

    k_init<<<gN, 256>>>(Nn);
    k_detect<<<32, 1024>>>((const unsigned int*)ei, 2 * E);
    k_convert<<<gE, 256>>>(ei, E);
    k_count<<<gE, 256>>>(E);
    k_dinv<<<gN, 256>>>(Nn);
    k_scan1<<<NB, 1024>>>(Nn);
    k_scan2<<<1, 64>>>(NB);
    k_scan3<<<gN, 256>>>(Nn, E);
    k_scatter<<<gE, 256>>>(E);

    int gGemm = (Nn + 63) / 64;
    int gAgg  = (Nn + 7) / 8;

    k_gemm1<<<gGemm, 256>>>(x, W1, Nn);          // buf1 = x @ W1
    k_agg<<<gAgg, 256>>>(b1, Nn);                // buf2 = agg(buf1) + b1
    k_gemm2<<<gGemm, 256>>>(W2, Nn);             // buf1 = buf2 @ W2
    k_agg<<<gAgg, 256>>>(b2, Nn);                // buf2 = agg(buf1) + b2
    k_fc<<<(Nn * 8 + 255) / 256, 256>>>(Wfc, bfc, out, Nn);
}

// round 13
// speedup vs baseline: 2.2488x; 2.2488x over previous
#include <cuda_runtime.h>

#define FDIM 128
#define MAXN 50000
#define MAXE 800000

// ---------------- scratch (static device globals; no allocation) ------------
__device__ int   g_flag;                 // 1 => edge_index is int32, 0 => int64
__device__ int   g_row[MAXE];
__device__ int   g_col[MAXE];
__device__ int   g_srt[MAXE];            // edge sources sorted by destination (CSR)
__device__ int   g_cnt[MAXN];
__device__ int   g_cstart[MAXN + 1];
__device__ int   g_cursor[MAXN];
__device__ int   g_bsum[64];
__device__ int   g_boff[64];
__device__ float g_dinv[MAXN];
__device__ float g_s[MAXN];              // s_j = dj*(dj + sum_r dr)  (= (A·1)_j)
__device__ float g_wb2[FDIM * 8];        // W2 @ Wfc
__device__ float g_wbig[FDIM * 8];       // W1 @ W2 @ Wfc
__device__ float g_v1[8];                // b1 @ W2 @ Wfc
__device__ float g_v2[8];                // b2 @ Wfc + bfc
__device__ float g_small[(size_t)MAXN * 8];  // x @ Wbig
__device__ float g_ybuf[(size_t)MAXN * 8];   // A @ small

// ---------------- setup kernels --------------------------------------------
__global__ void k_init(int Nn) {
    int i = blockIdx.x * blockDim.x + threadIdx.x;
    if (i < Nn) g_cnt[i] = 0;
    if (i == 0) g_flag = 0;
}

// int64 vs int32 dtype sniff: for little-endian int64 node ids < 2^31 every
// odd 32-bit word is zero; for int32 the odd words are random node ids.
__global__ void k_detect(const unsigned int* __restrict__ buf, int nwords) {
    int i = blockIdx.x * blockDim.x + threadIdx.x;   // 0 .. 32767
    int idx = 2 * i + 1;
    if (idx < nwords && buf[idx] != 0u) g_flag = 1;  // benign race, all write 1
}

// convert to int32 + per-destination degree count in one pass
__global__ void k_convert_count(const void* __restrict__ buf, int E) {
    int e = blockIdx.x * blockDim.x + threadIdx.x;
    if (e >= E) return;
    int r, c;
    if (g_flag == 0) {
        const long long* p = (const long long*)buf;
        r = (int)p[e];
        c = (int)p[(size_t)E + e];
    } else {
        const int* p = (const int*)buf;
        r = p[e];
        c = p[E + e];
    }
    g_row[e] = r;
    g_col[e] = c;
    atomicAdd(&g_cnt[c], 1);
}

// ---------------- exclusive scan over g_cnt (N <= 50000) + dinv -------------
__global__ void k_scan1(int Nn) {
    __shared__ int s[1024];
    int tid = threadIdx.x;
    int i = blockIdx.x * 1024 + tid;
    int v = (i < Nn) ? g_cnt[i] : 0;
    s[tid] = v;
    __syncthreads();
    for (int off = 1; off < 1024; off <<= 1) {
        int t = (tid >= off) ? s[tid - off] : 0;
        __syncthreads();
        s[tid] += t;
        __syncthreads();
    }
    if (i < Nn) {
        g_cstart[i] = s[tid] - v;                    // block-local exclusive
        g_dinv[i] = rsqrtf((float)(v + 1));          // +1 self loop
    }
    if (tid == 1023) g_bsum[blockIdx.x] = s[1023];
}

__global__ void k_scan2(int NB) {
    __shared__ int s[64];
    int tid = threadIdx.x;
    int v = (tid < NB) ? g_bsum[tid] : 0;
    s[tid] = v;
    __syncthreads();
    for (int off = 1; off < 64; off <<= 1) {
        int t = (tid >= off) ? s[tid - off] : 0;
        __syncthreads();
        s[tid] += t;
        __syncthreads();
    }
    g_boff[tid] = s[tid] - v;
}

__global__ void k_scan3(int Nn, int E) {
    int i = blockIdx.x * blockDim.x + threadIdx.x;
    if (i < Nn) {
        int v = g_cstart[i] + g_boff[i >> 10];
        g_cstart[i] = v;
        g_cursor[i] = v;
    }
    if (i == 0) g_cstart[Nn] = E;
}

__global__ void k_scatter(int E) {
    int e = blockIdx.x * blockDim.x + threadIdx.x;
    if (e < E) {
        int c = g_col[e];
        int p = atomicAdd(&g_cursor[c], 1);
        g_srt[p] = g_row[e];
    }
}

// ---------------- weight collapse: Wbig = W1@W2@Wfc, v1, v2 ----------------
__global__ void __launch_bounds__(1024)
k_wp1(const float* __restrict__ W2, const float* __restrict__ Wfc) {
    int r = threadIdx.x >> 3, c = threadIdx.x & 7;   // 128 x 8
    float acc = 0.f;
#pragma unroll 8
    for (int k = 0; k < 128; k++) acc += W2[r * 128 + k] * Wfc[k * 8 + c];
    g_wb2[r * 8 + c] = acc;
}

__global__ void __launch_bounds__(1024)
k_wp2(const float* __restrict__ W1, const float* __restrict__ b1,
      const float* __restrict__ b2, const float* __restrict__ Wfc,
      const float* __restrict__ bfc) {
    int r = threadIdx.x >> 3, c = threadIdx.x & 7;
    float acc = 0.f;
#pragma unroll 8
    for (int k = 0; k < 128; k++) acc += W1[r * 128 + k] * g_wb2[k * 8 + c];
    g_wbig[r * 8 + c] = acc;
    if (threadIdx.x < 8) {
        float v = 0.f, u = 0.f;
        for (int k = 0; k < 128; k++) {
            v += b1[k] * g_wb2[k * 8 + threadIdx.x];
            u += b2[k] * Wfc[k * 8 + threadIdx.x];
        }
        g_v1[threadIdx.x] = v;
        g_v2[threadIdx.x] = u + bfc[threadIdx.x];
    }
}

// ---------------- small = x @ Wbig  [N,8] -----------------------------------
__global__ void __launch_bounds__(256)
k_small(const float* __restrict__ x, int Nn) {
    __shared__ float Ws[FDIM * 8];
    for (int i = threadIdx.x; i < FDIM * 8; i += 256) Ws[i] = g_wbig[i];
    __syncthreads();
    int gid = blockIdx.x * blockDim.x + threadIdx.x;
    int n = gid >> 3, c = gid & 7;
    if (n >= Nn) return;
    const float4* xp = (const float4*)(x + (size_t)n * FDIM);
    float acc = 0.f;
#pragma unroll
    for (int k4 = 0; k4 < 32; k4++) {
        float4 v = xp[k4];
        acc += v.x * Ws[(k4 * 4 + 0) * 8 + c];
        acc += v.y * Ws[(k4 * 4 + 1) * 8 + c];
        acc += v.z * Ws[(k4 * 4 + 2) * 8 + c];
        acc += v.w * Ws[(k4 * 4 + 3) * 8 + c];
    }
    g_small[gid] = acc;
}

// ---------------- 8-wide aggregation: out[j] = (A·in)[j] --------------------
// Thread per destination node. Buffers are selected INSIDE the kernel
// (device globals are not valid as host-side kernel args). pass=0:
// g_small -> g_ybuf, also computes s_j. pass=1: g_ybuf -> out_ext, adds
// s_j*v1 + v2 (bias fold). Next (srt, dinv) pair prefetched one iteration
// ahead to overlap the index chain with the float4 gathers.
__global__ void __launch_bounds__(256)
k_agg8(float* __restrict__ out_ext, int Nn, int pass) {
    int j = blockIdx.x * blockDim.x + threadIdx.x;
    if (j >= Nn) return;
    const float4* in4 = (const float4*)(pass ? g_ybuf : g_small);
    float dj = g_dinv[j];
    float4 a0 = in4[2 * j], a1 = in4[2 * j + 1];
    float w0 = dj * dj;                              // self loop
    float4 c0, c1;
    c0.x = w0 * a0.x; c0.y = w0 * a0.y; c0.z = w0 * a0.z; c0.w = w0 * a0.w;
    c1.x = w0 * a1.x; c1.y = w0 * a1.y; c1.z = w0 * a1.z; c1.w = w0 * a1.w;
    float dsum = 0.f;
    int s = g_cstart[j], e = g_cstart[j + 1];
    if (s < e) {
        int   r_nxt = __ldg(&g_srt[s]);
        float d_nxt = __ldg(&g_dinv[r_nxt]);
        for (int idx = s; idx < e; ++idx) {
            int   r  = r_nxt;
            float dr = d_nxt;
            if (idx + 1 < e) {
                r_nxt = __ldg(&g_srt[idx + 1]);
                d_nxt = __ldg(&g_dinv[r_nxt]);
            }
            dsum += dr;
            float w = dj * dr;
            float4 h0 = in4[2 * r], h1 = in4[2 * r + 1];
            c0.x += w * h0.x; c0.y += w * h0.y; c0.z += w * h0.z; c0.w += w * h0.w;
            c1.x += w * h1.x; c1.y += w * h1.y; c1.z += w * h1.z; c1.w += w * h1.w;
        }
    }
    float4* o4;
    if (!pass) {
        g_s[j] = dj * (dj + dsum);
        o4 = (float4*)g_ybuf;
    } else {
        float sj = g_s[j];
        c0.x += sj * g_v1[0] + g_v2[0];
        c0.y += sj * g_v1[1] + g_v2[1];
        c0.z += sj * g_v1[2] + g_v2[2];
        c0.w += sj * g_v1[3] + g_v2[3];
        c1.x += sj * g_v1[4] + g_v2[4];
        c1.y += sj * g_v1[5] + g_v2[5];
        c1.z += sj * g_v1[6] + g_v2[6];
        c1.w += sj * g_v1[7] + g_v2[7];
        o4 = (float4*)out_ext;
    }
    o4[2 * j] = c0;
    o4[2 * j + 1] = c1;
}

// ---------------- launch ----------------------------------------------------
extern "C" void kernel_launch(void* const* d_in, const int* in_sizes, int n_in,
                              void* d_out, int out_size) {
    const float* x   = (const float*)d_in[0];
    const void*  ei  = d_in[1];
    const float* W1  = (const float*)d_in[2];
    const float* b1  = (const float*)d_in[3];
    const float* W2  = (const float*)d_in[4];
    const float* b2  = (const float*)d_in[5];
    const float* Wfc = (const float*)d_in[6];
    const float* bfc = (const float*)d_in[7];
    float* out = (float*)d_out;

    int Nn = in_sizes[0] / FDIM;
    int E  = in_sizes[1] / 2;
    if (Nn > MAXN) Nn = MAXN;
    if (E > MAXE)  E = MAXE;

    int gE = (E + 255) / 256;
    int gN = (Nn + 255) / 256;
    int NB = (Nn + 1023) / 1024;

    // CSR build
    k_init<<<gN, 256>>>(Nn);
    k_detect<<<32, 1024>>>((const unsigned int*)ei, 2 * E);
    k_convert_count<<<gE, 256>>>(ei, E);
    k_scan1<<<NB, 1024>>>(Nn);
    k_scan2<<<1, 64>>>(NB);
    k_scan3<<<gN, 256>>>(Nn, E);
    k_scatter<<<gE, 256>>>(E);

    // collapsed weights + projected features
    k_wp1<<<1, 1024>>>(W2, Wfc);
    k_wp2<<<1, 1024>>>(W1, b1, b2, Wfc, bfc);
    k_small<<<(Nn * 8 + 255) / 256, 256>>>(x, Nn);

    // out = A*(A*small) + s*v1 + v2
    k_agg8<<<gN, 256>>>(out, Nn, 0);
    k_agg8<<<gN, 256>>>(out, Nn, 1);
}